// round 16
// baseline (speedup 1.0000x reference)
#include <cuda_runtime.h>

#define BB 128
#define CC 1000
#define DD 300
#define LL 40
#define HH 100

typedef unsigned long long ull;

// ---------------- scratch (device globals) -----------------------------------
__device__ float g_fu[BB * DD];                 // final_utt [B,D]
__device__ float g_cand_t[DD * CC];             // sigmoid(cand transform) TRANSPOSED [d][c]
__device__ float g_M1[DD * DD];                 // sys_slots^T @ final_utt [D,D]
__device__ float g_mr[CC * DD];                 // request gate matrix [C,D]
__device__ float g_mc[CC * DD];                 // confirm gate matrix [C,D]
__device__ float g_Pc[CC * BB];                 // (slot@confS^T)*(value@confV^T) [C,B]
__device__ float g_y23[2 * CC];                 // y2[c], y3[c]
__device__ uint2 g_Bfrag[8320];                 // Wd bf16 B-frags [ch10][ks2][nt13][lane]
__device__ uint2 g_WfragC[38 * 240 * 32];       // conv W tf32 B-frags [kc 38][nt 240][lane]

// ---------------- helpers ----------------------------------------------------
__device__ __forceinline__ float sigf(float x) {          // exact-ish (MUFU x2)
    return __fdividef(1.f, 1.f + __expf(-x));
}
__device__ __forceinline__ float sigt(float x) {          // tanh-based (MUFU x1)
    float t;
    asm("tanh.approx.f32 %0, %1;" : "=f"(t) : "f"(0.5f * x));
    return fmaf(0.5f, t, 0.5f);
}
__device__ __forceinline__ ull ld2(const float* p) {
    return *reinterpret_cast<const ull*>(p);
}
__device__ __forceinline__ float lo2(ull v) { return __int_as_float((unsigned)v); }
__device__ __forceinline__ float hi2(ull v) { return __int_as_float((unsigned)(v >> 32)); }
__device__ __forceinline__ float psum(ull v) { return lo2(v) + hi2(v); }
__device__ __forceinline__ void fma2(ull& d, ull a, ull b) {
    asm("fma.rn.f32x2 %0, %1, %2, %0;" : "+l"(d) : "l"(a), "l"(b));
}
__device__ __forceinline__ float wredsum(float v) {
    #pragma unroll
    for (int o = 16; o; o >>= 1) v += __shfl_xor_sync(0xffffffffu, v, o);
    return v;
}
__device__ __forceinline__ unsigned tf32(float x) {
    unsigned r;
    asm("cvt.rna.tf32.f32 %0, %1;" : "=r"(r) : "f"(x));
    return r;
}
__device__ __forceinline__ unsigned bf2(float lo, float hi) {
    unsigned r;
    asm("cvt.rn.bf16x2.f32 %0, %1, %2;" : "=r"(r) : "f"(hi), "f"(lo));
    return r;
}
__device__ __forceinline__ void mma_tf32(float& c0, float& c1, float& c2, float& c3,
                                         unsigned a0, unsigned a1, unsigned a2, unsigned a3,
                                         unsigned b0, unsigned b1) {
    asm("mma.sync.aligned.m16n8k8.row.col.f32.tf32.tf32.f32 "
        "{%0,%1,%2,%3},{%4,%5,%6,%7},{%8,%9},{%0,%1,%2,%3};"
        : "+f"(c0), "+f"(c1), "+f"(c2), "+f"(c3)
        : "r"(a0), "r"(a1), "r"(a2), "r"(a3), "r"(b0), "r"(b1));
}
__device__ __forceinline__ void mma_bf16(float& c0, float& c1, float& c2, float& c3,
                                         unsigned a0, unsigned a1, unsigned a2, unsigned a3,
                                         unsigned b0, unsigned b1) {
    asm("mma.sync.aligned.m16n8k16.row.col.f32.bf16.bf16.f32 "
        "{%0,%1,%2,%3},{%4,%5,%6,%7},{%8,%9},{%0,%1,%2,%3};"
        : "+f"(c0), "+f"(c1), "+f"(c2), "+f"(c3)
        : "r"(a0), "r"(a1), "r"(a2), "r"(a3), "r"(b0), "r"(b1));
}

// ---------------- 1a) repack_conv: conv W tf32 frags (critical path) ----------
#define N_WC  (38 * 240 * 32)
#define N_BF  8320
#define N_M1  (DD * DD)
__global__ void repack_conv_kernel(const float* __restrict__ w1,
                                   const float* __restrict__ w2,
                                   const float* __restrict__ w3) {
    int idx = blockIdx.x * 256 + threadIdx.x;
    if (idx >= N_WC) return;
    int lane = idx & 31;
    int tmp  = idx >> 5;
    int nt   = tmp % 240;
    int kc   = tmp / 240;
    int q = lane & 3, r = lane >> 2;
    int col = nt * 8 + r;
    int f = col / 6, tap = col % 6;
    int d0 = kc * 8 + q, d1 = d0 + 4;
    uint2 u = {0u, 0u};
    if (f < DD) {
        int b0 = f * DD;
        float v0 = 0.f, v1 = 0.f;
        if (tap == 0) {
            if (d0 < DD) v0 = w1[b0 + d0];
            if (d1 < DD) v1 = w1[b0 + d1];
        } else if (tap <= 2) {
            if (d0 < DD) v0 = w2[(b0 + d0) * 2 + (tap - 1)];
            if (d1 < DD) v1 = w2[(b0 + d1) * 2 + (tap - 1)];
        } else {
            if (d0 < DD) v0 = w3[(b0 + d0) * 3 + (tap - 3)];
            if (d1 < DD) v1 = w3[(b0 + d1) * 3 + (tap - 3)];
        }
        u.x = tf32(v0);
        u.y = tf32(v1);
    }
    g_WfragC[idx] = u;
}

// ---------------- 1b) repack_rest: Wd bf16 B-frags + zero M1 (off-path) -------
__global__ void repack_rest_kernel(const float* __restrict__ Wd) {
    int idx = blockIdx.x * 256 + threadIdx.x;
    if (idx < N_BF) {
        int lane = idx & 31;
        int tmp  = idx >> 5;
        int nt   = tmp % 13;
        int tmp2 = tmp / 13;
        int ks   = tmp2 & 1;
        int ch   = tmp2 >> 1;                // 0..9
        int q = lane & 3, r = lane >> 2;
        int d0 = ch * 32 + ks * 16 + 2 * q;
        int h  = nt * 8 + r;
        float vx0 = 0.f, vx1 = 0.f, vy0 = 0.f, vy1 = 0.f;
        if (h < HH) {
            const float* wp = Wd + h * DD;
            if (d0 < DD)     vx0 = wp[d0];
            if (d0 + 1 < DD) vx1 = wp[d0 + 1];
            if (d0 + 8 < DD) vy0 = wp[d0 + 8];
            if (d0 + 9 < DD) vy1 = wp[d0 + 9];
        }
        uint2 u;
        u.x = bf2(vx0, vx1);
        u.y = bf2(vy0, vy1);
        g_Bfrag[idx] = u;
    } else if (idx < N_BF + N_M1) {
        g_M1[idx - N_BF] = 0.f;
    }
}

// ---------------- 2) CNN encoder: tf32 mma.sync, pipelined B-frags ------------
// SX ≡ 4 (mod 32) -> A-frag LDS banks = 4r+q, conflict-free.
#define SX 308
__global__ void __launch_bounds__(256, 2) conv_kernel(
        const float* __restrict__ utt,
        const float* __restrict__ cb1,
        const float* __restrict__ cb2,
        const float* __restrict__ cb3) {
    extern __shared__ unsigned Xs[];   // [48][SX] tf32; reused as float Gs[48][196]
    int t = threadIdx.x, lane = t & 31, w = t >> 5;
    int q = lane & 3, r = lane >> 2;
    int ncg = blockIdx.x;              // col-group: 384 F' cols
    int b   = blockIdx.y;

    for (int i = t; i < 48 * SX; i += 256) Xs[i] = 0u;
    __syncthreads();
    const float* xp = utt + b * (LL * DD);
    for (int i = t; i < LL * DD; i += 256) {
        int l = i / DD, d = i % DD;
        Xs[l * SX + d] = tf32(xp[i]);
    }
    __syncthreads();

    float acc[3][6][4];
    #pragma unroll
    for (int mt = 0; mt < 3; mt++)
        #pragma unroll
        for (int n = 0; n < 6; n++)
            #pragma unroll
            for (int k = 0; k < 4; k++) acc[mt][n][k] = 0.f;

    int nt0 = ncg * 48 + w * 6;
    const uint2* wfp = g_WfragC + nt0 * 32 + lane;

    uint2 bfc[6];
    #pragma unroll
    for (int n = 0; n < 6; n++) bfc[n] = wfp[n * 32];

    #pragma unroll 2
    for (int kc = 0; kc < 38; kc++) {
        unsigned a[3][4];
        int cb0 = kc * 8 + q;
        #pragma unroll
        for (int mt = 0; mt < 3; mt++) {
            int row = mt * 16 + r;
            a[mt][0] = Xs[row * SX + cb0];
            a[mt][1] = Xs[(row + 8) * SX + cb0];
            a[mt][2] = Xs[row * SX + cb0 + 4];
            a[mt][3] = Xs[(row + 8) * SX + cb0 + 4];
        }
        uint2 bfn[6];
        if (kc < 37) {
            const uint2* wn = wfp + 240 * 32;
            #pragma unroll
            for (int n = 0; n < 6; n++) bfn[n] = wn[n * 32];
        }
        #pragma unroll
        for (int mt = 0; mt < 3; mt++)
            #pragma unroll
            for (int n = 0; n < 6; n++)
                mma_tf32(acc[mt][n][0], acc[mt][n][1], acc[mt][n][2], acc[mt][n][3],
                         a[mt][0], a[mt][1], a[mt][2], a[mt][3], bfc[n].x, bfc[n].y);
        #pragma unroll
        for (int n = 0; n < 6; n++) bfc[n] = bfn[n];
        wfp += 240 * 32;
    }

    float* Gs = reinterpret_cast<float*>(Xs);
    #pragma unroll
    for (int ph = 0; ph < 2; ph++) {
        __syncthreads();
        if ((w >> 2) == ph) {
            int colb = (w & 3) * 48 + 2 * q;
            #pragma unroll
            for (int mt = 0; mt < 3; mt++) {
                int row = mt * 16 + r;
                #pragma unroll
                for (int n = 0; n < 6; n++) {
                    int col = colb + n * 8;
                    *reinterpret_cast<float2*>(&Gs[row * 196 + col]) =
                        make_float2(acc[mt][n][0], acc[mt][n][1]);
                    *reinterpret_cast<float2*>(&Gs[(row + 8) * 196 + col]) =
                        make_float2(acc[mt][n][2], acc[mt][n][3]);
                }
            }
        }
        __syncthreads();
        if (t < 32) {
            int f = ncg * 64 + ph * 32 + t;
            if (f < DD) {
                float z1 = -1e30f, z2 = -1e30f, z3 = -1e30f;
                #pragma unroll
                for (int l = 0; l < 40; l++) z1 = fmaxf(z1, Gs[l * 196 + t * 6 + 0]);
                #pragma unroll
                for (int l = 0; l < 39; l++)
                    z2 = fmaxf(z2, Gs[l * 196 + t * 6 + 1] + Gs[(l + 1) * 196 + t * 6 + 2]);
                #pragma unroll
                for (int l = 0; l < 38; l++)
                    z3 = fmaxf(z3, Gs[l * 196 + t * 6 + 3] + Gs[(l + 1) * 196 + t * 6 + 4]
                                   + Gs[(l + 2) * 196 + t * 6 + 5]);
                g_fu[b * DD + f] = fmaxf(z1 + cb1[f], 0.f) + fmaxf(z2 + cb2[f], 0.f)
                                 + fmaxf(z3 + cb3[f], 0.f);
            }
        }
    }
}

// ---------------- 3) candidate transform -> TRANSPOSED output -----------------
__global__ void cand_kernel(const float* __restrict__ slot,
                            const float* __restrict__ val,
                            const float* __restrict__ Wc,
                            const float* __restrict__ bc) {
    __shared__ __align__(8) float As[16][32];
    __shared__ __align__(8) float Ws[128][34];
    int t = threadIdx.x, tx = t & 31, ty = t >> 5;
    int c0 = blockIdx.x * 16, j0 = blockIdx.y * 128;

    ull acc[2][4];
    #pragma unroll
    for (int m = 0; m < 2; m++)
        #pragma unroll
        for (int k = 0; k < 4; k++) acc[m][k] = 0ull;

    for (int k0 = 0; k0 < 600; k0 += 32) {
        __syncthreads();
        #pragma unroll
        for (int i = 0; i < 2; i++) {
            int idx = t + i * 256;
            int row = idx >> 5, kk = idx & 31;
            int c = c0 + row, k = k0 + kk;
            float v = 0.f;
            if (c < CC) v = (k < DD) ? slot[c * DD + k] : val[c * DD + k - DD];
            As[row][kk] = v;
        }
        #pragma unroll
        for (int i = 0; i < 16; i++) {
            int idx = t + i * 256;
            int jj = idx >> 5, kk = idx & 31;
            int j = j0 + jj, k = k0 + kk;
            Ws[jj][kk] = (j < DD) ? Wc[j * 600 + k] : 0.f;
        }
        __syncthreads();
        #pragma unroll
        for (int p = 0; p < 16; p++) {
            ull a2[2], w2[4];
            #pragma unroll
            for (int m = 0; m < 2; m++) a2[m] = ld2(&As[ty + 8 * m][2 * p]);
            #pragma unroll
            for (int k = 0; k < 4; k++) w2[k] = ld2(&Ws[tx + 32 * k][2 * p]);
            #pragma unroll
            for (int m = 0; m < 2; m++)
                #pragma unroll
                for (int k = 0; k < 4; k++) fma2(acc[m][k], a2[m], w2[k]);
        }
    }
    #pragma unroll
    for (int m = 0; m < 2; m++)
        #pragma unroll
        for (int k = 0; k < 4; k++) {
            int c = c0 + ty + 8 * m;
            int j = j0 + tx + 32 * k;
            if (c < CC && j < DD)
                g_cand_t[j * CC + c] = sigf(psum(acc[m][k]) + bc[j]);
        }
}

// ---------------- 4) M1 = sys_slots^T @ final_utt ------------------------------
__global__ void m1_kernel(const float* __restrict__ sys) {
    int j = blockIdx.x * 128 + threadIdx.x;
    int i0 = blockIdx.y * 4;
    int b0 = blockIdx.z * 32;
    if (j >= DD) return;
    float acc[4] = {0.f, 0.f, 0.f, 0.f};
    #pragma unroll 4
    for (int b = b0; b < b0 + 32; b++) {
        float fv = g_fu[b * DD + j];
        #pragma unroll
        for (int ii = 0; ii < 4; ii++) acc[ii] += sys[b * DD + i0 + ii] * fv;
    }
    #pragma unroll
    for (int ii = 0; ii < 4; ii++) atomicAdd(&g_M1[(i0 + ii) * DD + j], acc[ii]);
}

// ---------------- 5) P_c[c,b] -------------------------------------------------
__global__ void pc_kernel(const float* __restrict__ slot,
                          const float* __restrict__ val,
                          const float* __restrict__ cs,
                          const float* __restrict__ cv) {
    __shared__ __align__(8) float Ss[64][32], Ve[64][32];
    __shared__ __align__(8) float Cs[64][34], Cv[64][34];
    int t = threadIdx.x, tx = t & 31, ty = t >> 5;
    int c0 = blockIdx.x * 64, b0 = blockIdx.y * 64;

    ull accA[8][2], accB[8][2];
    #pragma unroll
    for (int m = 0; m < 8; m++)
        #pragma unroll
        for (int k = 0; k < 2; k++) { accA[m][k] = 0ull; accB[m][k] = 0ull; }

    for (int d0 = 0; d0 < DD; d0 += 32) {
        __syncthreads();
        #pragma unroll
        for (int i = 0; i < 8; i++) {
            int idx = t + i * 256;
            int row = idx >> 5, dd = idx & 31;
            int d = d0 + dd;
            int c = c0 + row;
            bool okc = (c < CC && d < DD);
            Ss[row][dd] = okc ? slot[c * DD + d] : 0.f;
            Ve[row][dd] = okc ? val[c * DD + d] : 0.f;
            bool okb = (d < DD);
            Cs[row][dd] = okb ? cs[(b0 + row) * DD + d] : 0.f;
            Cv[row][dd] = okb ? cv[(b0 + row) * DD + d] : 0.f;
        }
        __syncthreads();
        #pragma unroll
        for (int p = 0; p < 16; p++) {
            ull aS[8], aV[8], wC[2], wV[2];
            #pragma unroll
            for (int m = 0; m < 8; m++) {
                aS[m] = ld2(&Ss[ty + 8 * m][2 * p]);
                aV[m] = ld2(&Ve[ty + 8 * m][2 * p]);
            }
            #pragma unroll
            for (int k = 0; k < 2; k++) {
                wC[k] = ld2(&Cs[tx + 32 * k][2 * p]);
                wV[k] = ld2(&Cv[tx + 32 * k][2 * p]);
            }
            #pragma unroll
            for (int m = 0; m < 8; m++)
                #pragma unroll
                for (int k = 0; k < 2; k++) {
                    fma2(accA[m][k], aS[m], wC[k]);
                    fma2(accB[m][k], aV[m], wV[k]);
                }
        }
    }
    #pragma unroll
    for (int m = 0; m < 8; m++)
        #pragma unroll
        for (int k = 0; k < 2; k++) {
            int c = c0 + ty + 8 * m;
            int b = b0 + tx + 32 * k;
            if (c < CC) g_Pc[c * BB + b] = psum(accA[m][k]) * psum(accB[m][k]);
        }
}

// ---------------- 6) generic A[M,K] @ B[K,300], mode = blockIdx.z --------------
__global__ void gemm_rn_kernel(const float* __restrict__ slotp) {
    int mode = blockIdx.z;
    const float* A  = mode ? g_Pc : slotp;
    const float* Bm = mode ? g_fu : g_M1;
    float* Out      = mode ? g_mc : g_mr;
    int K           = mode ? BB : DD;

    __shared__ __align__(8) float As[64][32];
    __shared__ __align__(8) float Bs[128][34];
    int t = threadIdx.x, tx = t & 31, ty = t >> 5;
    int m0 = blockIdx.x * 64, n0 = blockIdx.y * 128;

    ull acc[8][4];
    #pragma unroll
    for (int m = 0; m < 8; m++)
        #pragma unroll
        for (int k = 0; k < 4; k++) acc[m][k] = 0ull;

    int nch = (K + 31) >> 5;
    for (int ch = 0; ch < nch; ch++) {
        int k0 = ch * 32;
        __syncthreads();
        #pragma unroll
        for (int i = 0; i < 8; i++) {
            int idx = t + i * 256;
            int row = idx >> 5, kk = idx & 31;
            int m = m0 + row, k = k0 + kk;
            As[row][kk] = (m < CC && k < K) ? A[m * K + k] : 0.f;
        }
        #pragma unroll
        for (int i = 0; i < 16; i++) {
            int idx = t + i * 256;
            int nn = idx & 127, kk = idx >> 7;
            int n = n0 + nn, k = k0 + kk;
            Bs[nn][kk] = (k < K && n < DD) ? Bm[k * DD + n] : 0.f;
        }
        __syncthreads();
        #pragma unroll
        for (int p = 0; p < 16; p++) {
            ull a2[8], w2[4];
            #pragma unroll
            for (int m = 0; m < 8; m++) a2[m] = ld2(&As[ty + 8 * m][2 * p]);
            #pragma unroll
            for (int k = 0; k < 4; k++) w2[k] = ld2(&Bs[tx + 32 * k][2 * p]);
            #pragma unroll
            for (int m = 0; m < 8; m++)
                #pragma unroll
                for (int k = 0; k < 4; k++) fma2(acc[m][k], a2[m], w2[k]);
        }
    }
    #pragma unroll
    for (int m = 0; m < 8; m++)
        #pragma unroll
        for (int k = 0; k < 4; k++) {
            int mm = m0 + ty + 8 * m;
            int n = tx + 32 * k + n0;
            if (mm < CC && n < DD) Out[mm * DD + n] = psum(acc[m][k]);
        }
}

// ---------------- 7) y2/y3 ----------------------------------------------------
__global__ void y23_kernel(const float* __restrict__ Wmr, const float* __restrict__ bmr,
                           const float* __restrict__ Wmc, const float* __restrict__ bmc,
                           const float* __restrict__ Wj,  const float* __restrict__ bj) {
    int which = blockIdx.y;
    const float* Min = which ? g_mc : g_mr;
    const float* Wm  = which ? Wmc : Wmr;
    const float* bm  = which ? bmc : bmr;

    __shared__ __align__(8) float As[32][32];
    __shared__ __align__(8) float Ws[128][34];
    __shared__ float bmS[128], WjS[128];
    int t = threadIdx.x, tx = t & 31, ty = t >> 5;
    int c0 = blockIdx.x * 32;
    if (t < 128) {
        bmS[t] = (t < HH) ? bm[t] : 0.f;
        WjS[t] = (t < HH) ? Wj[t] : 0.f;
    }

    ull acc[4][4];
    #pragma unroll
    for (int m = 0; m < 4; m++)
        #pragma unroll
        for (int k = 0; k < 4; k++) acc[m][k] = 0ull;

    for (int d0 = 0; d0 < DD; d0 += 32) {
        __syncthreads();
        #pragma unroll
        for (int i = 0; i < 4; i++) {
            int idx = t + i * 256;
            int row = idx >> 5, dd = idx & 31;
            int c = c0 + row, d = d0 + dd;
            As[row][dd] = (c < CC && d < DD) ? sigf(Min[c * DD + d]) : 0.f;
        }
        #pragma unroll
        for (int i = 0; i < 16; i++) {
            int idx = t + i * 256;
            int h = idx >> 5, dd = idx & 31;
            int d = d0 + dd;
            Ws[h][dd] = (h < HH && d < DD) ? Wm[h * DD + d] : 0.f;
        }
        __syncthreads();
        #pragma unroll
        for (int p = 0; p < 16; p++) {
            ull a2[4], w2[4];
            #pragma unroll
            for (int m = 0; m < 4; m++) a2[m] = ld2(&As[ty + 8 * m][2 * p]);
            #pragma unroll
            for (int k = 0; k < 4; k++) w2[k] = ld2(&Ws[tx + 32 * k][2 * p]);
            #pragma unroll
            for (int m = 0; m < 4; m++)
                #pragma unroll
                for (int k = 0; k < 4; k++) fma2(acc[m][k], a2[m], w2[k]);
        }
    }
    float bjv = bj[0];
    #pragma unroll
    for (int m = 0; m < 4; m++) {
        float pv = 0.f;
        #pragma unroll
        for (int k = 0; k < 4; k++) {
            int h = tx + 32 * k;
            float hid = psum(acc[m][k]) + bmS[h];
            pv += sigf(hid) * WjS[h];
        }
        pv = wredsum(pv);
        if (tx == 0) {
            int c = c0 + ty + 8 * m;
            if (c < CC) g_y23[which * CC + c] = pv + bjv;
        }
    }
}

// ---------------- 8) main: bf16 mma, double-buffered, tanh sigmoid ------------
__global__ void __launch_bounds__(256, 2) main_kernel(
        const float* __restrict__ bd, const float* __restrict__ Wj,
        const float* __restrict__ bj, float* __restrict__ out) {
    __shared__ __align__(16) unsigned ActS[2][16 * 136];  // bf16x2 act, double-buffered
    __shared__ float fuS[304];
    __shared__ float bdS[104], WjS[104];

    int t = threadIdx.x;
    int lane = t & 31, wid = t >> 5;
    int q = lane & 3, r = lane >> 2;
    int c0 = blockIdx.x * 128;
    int b  = blockIdx.y;

    if (t < 104) {
        bdS[t] = (t < HH) ? bd[t] : 0.f;
        WjS[t] = (t < HH) ? Wj[t] : 0.f;
    }
    for (int i = t; i < DD; i += 256) fuS[i] = g_fu[b * DD + i];

    float acc[13][4];
    #pragma unroll
    for (int nt = 0; nt < 13; nt++)
        #pragma unroll
        for (int k = 0; k < 4; k++) acc[nt][k] = 0.f;

    int cb   = wid * 16;
    int half = t >> 7;             // 0 or 1: which 8 dpairs this thread builds
    int cl   = t & 127;
    int c    = c0 + cl;
    if (c >= CC) c = CC - 1;       // clamp: garbage rows never stored
    const float* cp = g_cand_t + c;

    // rv holds act inputs for the chunk about to be built
    float rv[16];
    #pragma unroll
    for (int i = 0; i < 16; i++) rv[i] = cp[(half * 16 + i) * CC];

    // need fuS before first build
    __syncthreads();
    // build chunk 0 into buf 0
    {
        unsigned* as = &ActS[0][(half * 8) * 136 + cl];
        int dbase = half * 16;
        #pragma unroll
        for (int i = 0; i < 8; i++) {
            float aL = sigt(rv[2 * i]     * fuS[dbase + 2 * i]);
            float aH = sigt(rv[2 * i + 1] * fuS[dbase + 2 * i + 1]);
            as[i * 136] = bf2(aL, aH);
        }
    }
    // load rv for chunk 1
    {
        const float* pn = cp + (32 + half * 16) * CC;
        #pragma unroll
        for (int i = 0; i < 16; i++) rv[i] = pn[i * CC];
    }

    for (int ch = 0; ch < 10; ch++) {
        __syncthreads();                 // buf[ch&1] built by all; buf[(ch+1)&1] free
        // MMA phase on buf[ch&1]
        const unsigned* ab = ActS[ch & 1];
        #pragma unroll
        for (int ks = 0; ks < 2; ks++) {
            int dp = ks * 8 + q;
            unsigned a0 = ab[dp * 136 + cb + r];
            unsigned a1 = ab[dp * 136 + cb + r + 8];
            unsigned a2 = ab[(dp + 4) * 136 + cb + r];
            unsigned a3 = ab[(dp + 4) * 136 + cb + r + 8];
            const uint2* bp = &g_Bfrag[((ch * 2 + ks) * 13) * 32 + lane];
            uint2 bf[13];
            #pragma unroll
            for (int nt = 0; nt < 13; nt++) bf[nt] = bp[nt * 32];
            #pragma unroll
            for (int nt = 0; nt < 13; nt++)
                mma_bf16(acc[nt][0], acc[nt][1], acc[nt][2], acc[nt][3],
                         a0, a1, a2, a3, bf[nt].x, bf[nt].y);
        }
        // build chunk ch+1 into buf[(ch+1)&1]
        if (ch < 9) {
            unsigned* as = &ActS[(ch + 1) & 1][(half * 8) * 136 + cl];
            int dbase = (ch + 1) * 32 + half * 16;
            #pragma unroll
            for (int i = 0; i < 8; i++) {
                int d0 = dbase + 2 * i;
                int d1 = d0 + 1;
                float f0 = fuS[d0 < DD ? d0 : 0];
                float f1 = fuS[d1 < DD ? d1 : 0];
                float aL = sigt(rv[2 * i] * f0);
                float aH = sigt(rv[2 * i + 1] * f1);
                as[i * 136] = bf2(aL, aH);
            }
        }
        // prefetch rv for chunk ch+2 (latency hides under next MMA phase)
        if (ch < 7) {
            const float* pn = cp + ((ch + 2) * 32 + half * 16) * CC;
            #pragma unroll
            for (int i = 0; i < 16; i++) rv[i] = pn[i * CC];
        } else if (ch == 7) {
            int dbn = 288 + half * 16;
            #pragma unroll
            for (int i = 0; i < 16; i++) {
                int d = dbn + i;
                rv[i] = cp[(d < DD ? d : 0) * CC];
            }
        }
    }

    // epilogue
    float pA = 0.f, pB = 0.f;
    #pragma unroll
    for (int nt = 0; nt < 13; nt++) {
        int h0 = nt * 8 + 2 * q;
        float bd0 = bdS[h0], bd1 = bdS[h0 + 1];
        float wj0 = WjS[h0], wj1 = WjS[h0 + 1];
        pA += sigt(acc[nt][0] + bd0) * wj0 + sigt(acc[nt][1] + bd1) * wj1;
        pB += sigt(acc[nt][2] + bd0) * wj0 + sigt(acc[nt][3] + bd1) * wj1;
    }
    pA += __shfl_xor_sync(0xffffffffu, pA, 1);
    pA += __shfl_xor_sync(0xffffffffu, pA, 2);
    pB += __shfl_xor_sync(0xffffffffu, pB, 1);
    pB += __shfl_xor_sync(0xffffffffu, pB, 2);

    if (q == 0) {
        float bjv = bj[0];
        int c1 = c0 + cb + r;
        int c2 = c1 + 8;
        if (c1 < CC) out[b * CC + c1] = pA + bjv;
        if (c2 < CC) out[b * CC + c2] = pB + bjv;
    }
}

// ---------------- 9) finalize: out = 0.5*(y1+y2+y3) + 0.5*ypast ---------------
__global__ void finalize_kernel(const float* __restrict__ ypast,
                                float* __restrict__ out) {
    int idx = blockIdx.x * 256 + threadIdx.x;
    if (idx < BB * CC) {
        int cc = idx % CC;
        out[idx] = 0.5f * (out[idx] + g_y23[cc] + g_y23[CC + cc]) + 0.5f * ypast[idx];
    }
}

// ---------------- launch: capture-legal fork-join ------------------------------
extern "C" void kernel_launch(void* const* d_in, const int* in_sizes, int n_in,
                              void* d_out, int out_size) {
    const float* utt   = (const float*)d_in[0];
    const float* sys   = (const float*)d_in[1];
    const float* cs    = (const float*)d_in[2];
    const float* cv    = (const float*)d_in[3];
    const float* ypast = (const float*)d_in[4];
    const float* slot  = (const float*)d_in[5];
    const float* val   = (const float*)d_in[6];
    const float* Wc    = (const float*)d_in[7];
    const float* bc    = (const float*)d_in[8];
    const float* w1    = (const float*)d_in[9];
    const float* b1    = (const float*)d_in[10];
    const float* w2    = (const float*)d_in[11];
    const float* b2    = (const float*)d_in[12];
    const float* w3    = (const float*)d_in[13];
    const float* b3    = (const float*)d_in[14];
    const float* Wd    = (const float*)d_in[15];
    const float* bd    = (const float*)d_in[16];
    const float* Wmr   = (const float*)d_in[17];
    const float* bmr   = (const float*)d_in[18];
    const float* Wmc   = (const float*)d_in[19];
    const float* bmc   = (const float*)d_in[20];
    const float* Wj    = (const float*)d_in[21];
    const float* bj    = (const float*)d_in[22];
    float* out = (float*)d_out;

    static cudaStream_t s1 = nullptr, s2 = nullptr;
    static cudaEvent_t eFork, eCand, ePc, eConv, eY23;
    if (!s1) {
        // first call is the (uncaptured) correctness run: create infra once
        cudaStreamCreateWithFlags(&s1, cudaStreamNonBlocking);
        cudaStreamCreateWithFlags(&s2, cudaStreamNonBlocking);
        cudaEventCreateWithFlags(&eFork, cudaEventDisableTiming);
        cudaEventCreateWithFlags(&eCand, cudaEventDisableTiming);
        cudaEventCreateWithFlags(&ePc,   cudaEventDisableTiming);
        cudaEventCreateWithFlags(&eConv, cudaEventDisableTiming);
        cudaEventCreateWithFlags(&eY23,  cudaEventDisableTiming);
        cudaFuncSetAttribute(conv_kernel,
                             cudaFuncAttributeMaxDynamicSharedMemorySize, 48 * SX * 4);
    }

    // first captured work goes on stream 0, then FORK s1/s2 off it
    repack_conv_kernel<<<(N_WC + 255) / 256, 256>>>(w1, w2, w3);         // idx 0
    cudaEventRecord(eFork, 0);
    cudaStreamWaitEvent(s1, eFork, 0);
    cudaStreamWaitEvent(s2, eFork, 0);

    // branch s2: repack_rest (Bfrag + M1 zero) -> cand (off-path)
    repack_rest_kernel<<<(N_BF + N_M1 + 255) / 256, 256, 0, s2>>>(Wd);   // idx 1
    cand_kernel<<<dim3(63, 3), 256, 0, s2>>>(slot, val, Wc, bc);         // idx 2
    cudaEventRecord(eCand, s2);

    // main path on stream 0 (conv = 4th launch call -> ncu slot 3)
    conv_kernel<<<dim3(5, BB), 256, 48 * SX * 4>>>(utt, b1, b2, b3);     // idx 3 (ncu)
    cudaEventRecord(eConv, 0);
    pc_kernel<<<dim3(16, 2), 256, 0, s2>>>(slot, val, cs, cv);           // idx 4
    cudaEventRecord(ePc, s2);

    // side chain on s1: fu via eConv; Pc + M1-zero via ePc (s2 order)
    cudaStreamWaitEvent(s1, eConv, 0);
    cudaStreamWaitEvent(s1, ePc, 0);
    m1_kernel<<<dim3(3, 75, 4), 128, 0, s1>>>(sys);                      // idx 5
    gemm_rn_kernel<<<dim3(16, 3, 2), 256, 0, s1>>>(slot);                // idx 6
    y23_kernel<<<dim3(32, 2), 256, 0, s1>>>(Wmr, bmr, Wmc, bmc, Wj, bj); // idx 7
    cudaEventRecord(eY23, s1);

    // main on stream 0: after conv (program order) + cand/Bfrag (eCand)
    cudaStreamWaitEvent(0, eCand, 0);
    main_kernel<<<dim3(8, BB), 256>>>(bd, Wj, bj, out);                  // idx 8

    // JOIN: finalize after main (program order) + y23 (event)
    cudaStreamWaitEvent(0, eY23, 0);
    finalize_kernel<<<500, 256>>>(ypast, out);                           // idx 9
}

// round 17
// speedup vs baseline: 1.0919x; 1.0919x over previous
#include <cuda_runtime.h>

#define BB 128
#define CC 1000
#define DD 300
#define LL 40
#define HH 100

typedef unsigned long long ull;

// ---------------- scratch (device globals) -----------------------------------
__device__ float g_fu[BB * DD];                 // final_utt [B,D]
__device__ float g_cand_t[DD * CC];             // sigmoid(cand transform) TRANSPOSED [d][c]
__device__ float g_M1[DD * DD];                 // sys_slots^T @ final_utt [D,D]
__device__ float g_mr[CC * DD];                 // request gate matrix [C,D]
__device__ float g_mc[CC * DD];                 // confirm gate matrix [C,D]
__device__ float g_Pc[CC * BB];                 // (slot@confS^T)*(value@confV^T) [C,B]
__device__ float g_y23[2 * CC];                 // y2[c], y3[c]
__device__ uint2 g_Bfrag[8320];                 // Wd bf16 B-frags [ch10][ks2][nt13][lane]
__device__ uint2 g_WfragC[38 * 240 * 32];       // conv W tf32 B-frags [kc 38][nt 240][lane]

// ---------------- helpers ----------------------------------------------------
__device__ __forceinline__ float sigf(float x) {          // exact-ish (MUFU x2)
    return __fdividef(1.f, 1.f + __expf(-x));
}
__device__ __forceinline__ float sigt(float x) {          // tanh-based (MUFU x1)
    float t;
    asm("tanh.approx.f32 %0, %1;" : "=f"(t) : "f"(0.5f * x));
    return fmaf(0.5f, t, 0.5f);
}
__device__ __forceinline__ ull ld2(const float* p) {
    return *reinterpret_cast<const ull*>(p);
}
__device__ __forceinline__ float lo2(ull v) { return __int_as_float((unsigned)v); }
__device__ __forceinline__ float hi2(ull v) { return __int_as_float((unsigned)(v >> 32)); }
__device__ __forceinline__ float psum(ull v) { return lo2(v) + hi2(v); }
__device__ __forceinline__ void fma2(ull& d, ull a, ull b) {
    asm("fma.rn.f32x2 %0, %1, %2, %0;" : "+l"(d) : "l"(a), "l"(b));
}
__device__ __forceinline__ float wredsum(float v) {
    #pragma unroll
    for (int o = 16; o; o >>= 1) v += __shfl_xor_sync(0xffffffffu, v, o);
    return v;
}
__device__ __forceinline__ unsigned tf32(float x) {
    unsigned r;
    asm("cvt.rna.tf32.f32 %0, %1;" : "=r"(r) : "f"(x));
    return r;
}
__device__ __forceinline__ unsigned bf2(float lo, float hi) {
    unsigned r;
    asm("cvt.rn.bf16x2.f32 %0, %1, %2;" : "=r"(r) : "f"(hi), "f"(lo));
    return r;
}
__device__ __forceinline__ void mma_tf32(float& c0, float& c1, float& c2, float& c3,
                                         unsigned a0, unsigned a1, unsigned a2, unsigned a3,
                                         unsigned b0, unsigned b1) {
    asm("mma.sync.aligned.m16n8k8.row.col.f32.tf32.tf32.f32 "
        "{%0,%1,%2,%3},{%4,%5,%6,%7},{%8,%9},{%0,%1,%2,%3};"
        : "+f"(c0), "+f"(c1), "+f"(c2), "+f"(c3)
        : "r"(a0), "r"(a1), "r"(a2), "r"(a3), "r"(b0), "r"(b1));
}
__device__ __forceinline__ void mma_bf16(float& c0, float& c1, float& c2, float& c3,
                                         unsigned a0, unsigned a1, unsigned a2, unsigned a3,
                                         unsigned b0, unsigned b1) {
    asm("mma.sync.aligned.m16n8k16.row.col.f32.bf16.bf16.f32 "
        "{%0,%1,%2,%3},{%4,%5,%6,%7},{%8,%9},{%0,%1,%2,%3};"
        : "+f"(c0), "+f"(c1), "+f"(c2), "+f"(c3)
        : "r"(a0), "r"(a1), "r"(a2), "r"(a3), "r"(b0), "r"(b1));
}

// ---------------- 1a) repack_conv: conv W tf32 frags (critical path) ----------
#define N_WC  (38 * 240 * 32)
#define N_BF  8320
#define N_M1  (DD * DD)
__global__ void repack_conv_kernel(const float* __restrict__ w1,
                                   const float* __restrict__ w2,
                                   const float* __restrict__ w3) {
    int idx = blockIdx.x * 256 + threadIdx.x;
    if (idx >= N_WC) return;
    int lane = idx & 31;
    int tmp  = idx >> 5;
    int nt   = tmp % 240;
    int kc   = tmp / 240;
    int q = lane & 3, r = lane >> 2;
    int col = nt * 8 + r;
    int f = col / 6, tap = col % 6;
    int d0 = kc * 8 + q, d1 = d0 + 4;
    uint2 u = {0u, 0u};
    if (f < DD) {
        int b0 = f * DD;
        float v0 = 0.f, v1 = 0.f;
        if (tap == 0) {
            if (d0 < DD) v0 = w1[b0 + d0];
            if (d1 < DD) v1 = w1[b0 + d1];
        } else if (tap <= 2) {
            if (d0 < DD) v0 = w2[(b0 + d0) * 2 + (tap - 1)];
            if (d1 < DD) v1 = w2[(b0 + d1) * 2 + (tap - 1)];
        } else {
            if (d0 < DD) v0 = w3[(b0 + d0) * 3 + (tap - 3)];
            if (d1 < DD) v1 = w3[(b0 + d1) * 3 + (tap - 3)];
        }
        u.x = tf32(v0);
        u.y = tf32(v1);
    }
    g_WfragC[idx] = u;
}

// ---------------- 1b) repack_rest: Wd bf16 B-frags + zero M1 (off-path) -------
__global__ void repack_rest_kernel(const float* __restrict__ Wd) {
    int idx = blockIdx.x * 256 + threadIdx.x;
    if (idx < N_BF) {
        int lane = idx & 31;
        int tmp  = idx >> 5;
        int nt   = tmp % 13;
        int tmp2 = tmp / 13;
        int ks   = tmp2 & 1;
        int ch   = tmp2 >> 1;                // 0..9
        int q = lane & 3, r = lane >> 2;
        int d0 = ch * 32 + ks * 16 + 2 * q;
        int h  = nt * 8 + r;
        float vx0 = 0.f, vx1 = 0.f, vy0 = 0.f, vy1 = 0.f;
        if (h < HH) {
            const float* wp = Wd + h * DD;
            if (d0 < DD)     vx0 = wp[d0];
            if (d0 + 1 < DD) vx1 = wp[d0 + 1];
            if (d0 + 8 < DD) vy0 = wp[d0 + 8];
            if (d0 + 9 < DD) vy1 = wp[d0 + 9];
        }
        uint2 u;
        u.x = bf2(vx0, vx1);
        u.y = bf2(vy0, vy1);
        g_Bfrag[idx] = u;
    } else if (idx < N_BF + N_M1) {
        g_M1[idx - N_BF] = 0.f;
    }
}

// ---------------- 2) CNN encoder: tf32 mma.sync, b_base for b-split -----------
// SX ≡ 4 (mod 32) -> A-frag LDS banks = 4r+q, conflict-free.
#define SX 308
__global__ void __launch_bounds__(256, 2) conv_kernel(
        const float* __restrict__ utt,
        const float* __restrict__ cb1,
        const float* __restrict__ cb2,
        const float* __restrict__ cb3,
        int b_base) {
    extern __shared__ unsigned Xs[];   // [48][SX] tf32; reused as float Gs[48][196]
    int t = threadIdx.x, lane = t & 31, w = t >> 5;
    int q = lane & 3, r = lane >> 2;
    int ncg = blockIdx.x;              // col-group: 384 F' cols
    int b   = b_base + blockIdx.y;

    for (int i = t; i < 48 * SX; i += 256) Xs[i] = 0u;
    __syncthreads();
    const float* xp = utt + b * (LL * DD);
    for (int i = t; i < LL * DD; i += 256) {
        int l = i / DD, d = i % DD;
        Xs[l * SX + d] = tf32(xp[i]);
    }
    __syncthreads();

    float acc[3][6][4];
    #pragma unroll
    for (int mt = 0; mt < 3; mt++)
        #pragma unroll
        for (int n = 0; n < 6; n++)
            #pragma unroll
            for (int k = 0; k < 4; k++) acc[mt][n][k] = 0.f;

    int nt0 = ncg * 48 + w * 6;
    const uint2* wfp = g_WfragC + nt0 * 32 + lane;

    uint2 bfc[6];
    #pragma unroll
    for (int n = 0; n < 6; n++) bfc[n] = wfp[n * 32];

    #pragma unroll 2
    for (int kc = 0; kc < 38; kc++) {
        unsigned a[3][4];
        int cb0 = kc * 8 + q;
        #pragma unroll
        for (int mt = 0; mt < 3; mt++) {
            int row = mt * 16 + r;
            a[mt][0] = Xs[row * SX + cb0];
            a[mt][1] = Xs[(row + 8) * SX + cb0];
            a[mt][2] = Xs[row * SX + cb0 + 4];
            a[mt][3] = Xs[(row + 8) * SX + cb0 + 4];
        }
        uint2 bfn[6];
        if (kc < 37) {
            const uint2* wn = wfp + 240 * 32;
            #pragma unroll
            for (int n = 0; n < 6; n++) bfn[n] = wn[n * 32];
        }
        #pragma unroll
        for (int mt = 0; mt < 3; mt++)
            #pragma unroll
            for (int n = 0; n < 6; n++)
                mma_tf32(acc[mt][n][0], acc[mt][n][1], acc[mt][n][2], acc[mt][n][3],
                         a[mt][0], a[mt][1], a[mt][2], a[mt][3], bfc[n].x, bfc[n].y);
        #pragma unroll
        for (int n = 0; n < 6; n++) bfc[n] = bfn[n];
        wfp += 240 * 32;
    }

    float* Gs = reinterpret_cast<float*>(Xs);
    #pragma unroll
    for (int ph = 0; ph < 2; ph++) {
        __syncthreads();
        if ((w >> 2) == ph) {
            int colb = (w & 3) * 48 + 2 * q;
            #pragma unroll
            for (int mt = 0; mt < 3; mt++) {
                int row = mt * 16 + r;
                #pragma unroll
                for (int n = 0; n < 6; n++) {
                    int col = colb + n * 8;
                    *reinterpret_cast<float2*>(&Gs[row * 196 + col]) =
                        make_float2(acc[mt][n][0], acc[mt][n][1]);
                    *reinterpret_cast<float2*>(&Gs[(row + 8) * 196 + col]) =
                        make_float2(acc[mt][n][2], acc[mt][n][3]);
                }
            }
        }
        __syncthreads();
        if (t < 32) {
            int f = ncg * 64 + ph * 32 + t;
            if (f < DD) {
                float z1 = -1e30f, z2 = -1e30f, z3 = -1e30f;
                #pragma unroll
                for (int l = 0; l < 40; l++) z1 = fmaxf(z1, Gs[l * 196 + t * 6 + 0]);
                #pragma unroll
                for (int l = 0; l < 39; l++)
                    z2 = fmaxf(z2, Gs[l * 196 + t * 6 + 1] + Gs[(l + 1) * 196 + t * 6 + 2]);
                #pragma unroll
                for (int l = 0; l < 38; l++)
                    z3 = fmaxf(z3, Gs[l * 196 + t * 6 + 3] + Gs[(l + 1) * 196 + t * 6 + 4]
                                   + Gs[(l + 2) * 196 + t * 6 + 5]);
                g_fu[b * DD + f] = fmaxf(z1 + cb1[f], 0.f) + fmaxf(z2 + cb2[f], 0.f)
                                 + fmaxf(z3 + cb3[f], 0.f);
            }
        }
    }
}

// ---------------- 3) candidate transform -> TRANSPOSED output -----------------
__global__ void cand_kernel(const float* __restrict__ slot,
                            const float* __restrict__ val,
                            const float* __restrict__ Wc,
                            const float* __restrict__ bc) {
    __shared__ __align__(8) float As[16][32];
    __shared__ __align__(8) float Ws[128][34];
    int t = threadIdx.x, tx = t & 31, ty = t >> 5;
    int c0 = blockIdx.x * 16, j0 = blockIdx.y * 128;

    ull acc[2][4];
    #pragma unroll
    for (int m = 0; m < 2; m++)
        #pragma unroll
        for (int k = 0; k < 4; k++) acc[m][k] = 0ull;

    for (int k0 = 0; k0 < 600; k0 += 32) {
        __syncthreads();
        #pragma unroll
        for (int i = 0; i < 2; i++) {
            int idx = t + i * 256;
            int row = idx >> 5, kk = idx & 31;
            int c = c0 + row, k = k0 + kk;
            float v = 0.f;
            if (c < CC) v = (k < DD) ? slot[c * DD + k] : val[c * DD + k - DD];
            As[row][kk] = v;
        }
        #pragma unroll
        for (int i = 0; i < 16; i++) {
            int idx = t + i * 256;
            int jj = idx >> 5, kk = idx & 31;
            int j = j0 + jj, k = k0 + kk;
            Ws[jj][kk] = (j < DD) ? Wc[j * 600 + k] : 0.f;
        }
        __syncthreads();
        #pragma unroll
        for (int p = 0; p < 16; p++) {
            ull a2[2], w2[4];
            #pragma unroll
            for (int m = 0; m < 2; m++) a2[m] = ld2(&As[ty + 8 * m][2 * p]);
            #pragma unroll
            for (int k = 0; k < 4; k++) w2[k] = ld2(&Ws[tx + 32 * k][2 * p]);
            #pragma unroll
            for (int m = 0; m < 2; m++)
                #pragma unroll
                for (int k = 0; k < 4; k++) fma2(acc[m][k], a2[m], w2[k]);
        }
    }
    #pragma unroll
    for (int m = 0; m < 2; m++)
        #pragma unroll
        for (int k = 0; k < 4; k++) {
            int c = c0 + ty + 8 * m;
            int j = j0 + tx + 32 * k;
            if (c < CC && j < DD)
                g_cand_t[j * CC + c] = sigf(psum(acc[m][k]) + bc[j]);
        }
}

// ---------------- 4) M1 = sys_slots^T @ final_utt ------------------------------
__global__ void m1_kernel(const float* __restrict__ sys) {
    int j = blockIdx.x * 128 + threadIdx.x;
    int i0 = blockIdx.y * 4;
    int b0 = blockIdx.z * 32;
    if (j >= DD) return;
    float acc[4] = {0.f, 0.f, 0.f, 0.f};
    #pragma unroll 4
    for (int b = b0; b < b0 + 32; b++) {
        float fv = g_fu[b * DD + j];
        #pragma unroll
        for (int ii = 0; ii < 4; ii++) acc[ii] += sys[b * DD + i0 + ii] * fv;
    }
    #pragma unroll
    for (int ii = 0; ii < 4; ii++) atomicAdd(&g_M1[(i0 + ii) * DD + j], acc[ii]);
}

// ---------------- 5) P_c[c,b] -------------------------------------------------
__global__ void pc_kernel(const float* __restrict__ slot,
                          const float* __restrict__ val,
                          const float* __restrict__ cs,
                          const float* __restrict__ cv) {
    __shared__ __align__(8) float Ss[64][32], Ve[64][32];
    __shared__ __align__(8) float Cs[64][34], Cv[64][34];
    int t = threadIdx.x, tx = t & 31, ty = t >> 5;
    int c0 = blockIdx.x * 64, b0 = blockIdx.y * 64;

    ull accA[8][2], accB[8][2];
    #pragma unroll
    for (int m = 0; m < 8; m++)
        #pragma unroll
        for (int k = 0; k < 2; k++) { accA[m][k] = 0ull; accB[m][k] = 0ull; }

    for (int d0 = 0; d0 < DD; d0 += 32) {
        __syncthreads();
        #pragma unroll
        for (int i = 0; i < 8; i++) {
            int idx = t + i * 256;
            int row = idx >> 5, dd = idx & 31;
            int d = d0 + dd;
            int c = c0 + row;
            bool okc = (c < CC && d < DD);
            Ss[row][dd] = okc ? slot[c * DD + d] : 0.f;
            Ve[row][dd] = okc ? val[c * DD + d] : 0.f;
            bool okb = (d < DD);
            Cs[row][dd] = okb ? cs[(b0 + row) * DD + d] : 0.f;
            Cv[row][dd] = okb ? cv[(b0 + row) * DD + d] : 0.f;
        }
        __syncthreads();
        #pragma unroll
        for (int p = 0; p < 16; p++) {
            ull aS[8], aV[8], wC[2], wV[2];
            #pragma unroll
            for (int m = 0; m < 8; m++) {
                aS[m] = ld2(&Ss[ty + 8 * m][2 * p]);
                aV[m] = ld2(&Ve[ty + 8 * m][2 * p]);
            }
            #pragma unroll
            for (int k = 0; k < 2; k++) {
                wC[k] = ld2(&Cs[tx + 32 * k][2 * p]);
                wV[k] = ld2(&Cv[tx + 32 * k][2 * p]);
            }
            #pragma unroll
            for (int m = 0; m < 8; m++)
                #pragma unroll
                for (int k = 0; k < 2; k++) {
                    fma2(accA[m][k], aS[m], wC[k]);
                    fma2(accB[m][k], aV[m], wV[k]);
                }
        }
    }
    #pragma unroll
    for (int m = 0; m < 8; m++)
        #pragma unroll
        for (int k = 0; k < 2; k++) {
            int c = c0 + ty + 8 * m;
            int b = b0 + tx + 32 * k;
            if (c < CC) g_Pc[c * BB + b] = psum(accA[m][k]) * psum(accB[m][k]);
        }
}

// ---------------- 6) generic A[M,K] @ B[K,300], mode = blockIdx.z --------------
__global__ void gemm_rn_kernel(const float* __restrict__ slotp) {
    int mode = blockIdx.z;
    const float* A  = mode ? g_Pc : slotp;
    const float* Bm = mode ? g_fu : g_M1;
    float* Out      = mode ? g_mc : g_mr;
    int K           = mode ? BB : DD;

    __shared__ __align__(8) float As[64][32];
    __shared__ __align__(8) float Bs[128][34];
    int t = threadIdx.x, tx = t & 31, ty = t >> 5;
    int m0 = blockIdx.x * 64, n0 = blockIdx.y * 128;

    ull acc[8][4];
    #pragma unroll
    for (int m = 0; m < 8; m++)
        #pragma unroll
        for (int k = 0; k < 4; k++) acc[m][k] = 0ull;

    int nch = (K + 31) >> 5;
    for (int ch = 0; ch < nch; ch++) {
        int k0 = ch * 32;
        __syncthreads();
        #pragma unroll
        for (int i = 0; i < 8; i++) {
            int idx = t + i * 256;
            int row = idx >> 5, kk = idx & 31;
            int m = m0 + row, k = k0 + kk;
            As[row][kk] = (m < CC && k < K) ? A[m * K + k] : 0.f;
        }
        #pragma unroll
        for (int i = 0; i < 16; i++) {
            int idx = t + i * 256;
            int nn = idx & 127, kk = idx >> 7;
            int n = n0 + nn, k = k0 + kk;
            Bs[nn][kk] = (k < K && n < DD) ? Bm[k * DD + n] : 0.f;
        }
        __syncthreads();
        #pragma unroll
        for (int p = 0; p < 16; p++) {
            ull a2[8], w2[4];
            #pragma unroll
            for (int m = 0; m < 8; m++) a2[m] = ld2(&As[ty + 8 * m][2 * p]);
            #pragma unroll
            for (int k = 0; k < 4; k++) w2[k] = ld2(&Bs[tx + 32 * k][2 * p]);
            #pragma unroll
            for (int m = 0; m < 8; m++)
                #pragma unroll
                for (int k = 0; k < 4; k++) fma2(acc[m][k], a2[m], w2[k]);
        }
    }
    #pragma unroll
    for (int m = 0; m < 8; m++)
        #pragma unroll
        for (int k = 0; k < 4; k++) {
            int mm = m0 + ty + 8 * m;
            int n = tx + 32 * k + n0;
            if (mm < CC && n < DD) Out[mm * DD + n] = psum(acc[m][k]);
        }
}

// ---------------- 7) y2/y3 ----------------------------------------------------
__global__ void y23_kernel(const float* __restrict__ Wmr, const float* __restrict__ bmr,
                           const float* __restrict__ Wmc, const float* __restrict__ bmc,
                           const float* __restrict__ Wj,  const float* __restrict__ bj) {
    int which = blockIdx.y;
    const float* Min = which ? g_mc : g_mr;
    const float* Wm  = which ? Wmc : Wmr;
    const float* bm  = which ? bmc : bmr;

    __shared__ __align__(8) float As[32][32];
    __shared__ __align__(8) float Ws[128][34];
    __shared__ float bmS[128], WjS[128];
    int t = threadIdx.x, tx = t & 31, ty = t >> 5;
    int c0 = blockIdx.x * 32;
    if (t < 128) {
        bmS[t] = (t < HH) ? bm[t] : 0.f;
        WjS[t] = (t < HH) ? Wj[t] : 0.f;
    }

    ull acc[4][4];
    #pragma unroll
    for (int m = 0; m < 4; m++)
        #pragma unroll
        for (int k = 0; k < 4; k++) acc[m][k] = 0ull;

    for (int d0 = 0; d0 < DD; d0 += 32) {
        __syncthreads();
        #pragma unroll
        for (int i = 0; i < 4; i++) {
            int idx = t + i * 256;
            int row = idx >> 5, dd = idx & 31;
            int c = c0 + row, d = d0 + dd;
            As[row][dd] = (c < CC && d < DD) ? sigf(Min[c * DD + d]) : 0.f;
        }
        #pragma unroll
        for (int i = 0; i < 16; i++) {
            int idx = t + i * 256;
            int h = idx >> 5, dd = idx & 31;
            int d = d0 + dd;
            Ws[h][dd] = (h < HH && d < DD) ? Wm[h * DD + d] : 0.f;
        }
        __syncthreads();
        #pragma unroll
        for (int p = 0; p < 16; p++) {
            ull a2[4], w2[4];
            #pragma unroll
            for (int m = 0; m < 4; m++) a2[m] = ld2(&As[ty + 8 * m][2 * p]);
            #pragma unroll
            for (int k = 0; k < 4; k++) w2[k] = ld2(&Ws[tx + 32 * k][2 * p]);
            #pragma unroll
            for (int m = 0; m < 4; m++)
                #pragma unroll
                for (int k = 0; k < 4; k++) fma2(acc[m][k], a2[m], w2[k]);
        }
    }
    float bjv = bj[0];
    #pragma unroll
    for (int m = 0; m < 4; m++) {
        float pv = 0.f;
        #pragma unroll
        for (int k = 0; k < 4; k++) {
            int h = tx + 32 * k;
            float hid = psum(acc[m][k]) + bmS[h];
            pv += sigf(hid) * WjS[h];
        }
        pv = wredsum(pv);
        if (tx == 0) {
            int c = c0 + ty + 8 * m;
            if (c < CC) g_y23[which * CC + c] = pv + bjv;
        }
    }
}

// ---------------- 8) main: bf16 mma, double-buffered, b_base for b-split ------
__global__ void __launch_bounds__(256, 2) main_kernel(
        const float* __restrict__ bd, const float* __restrict__ Wj,
        const float* __restrict__ bj, float* __restrict__ out, int b_base) {
    __shared__ __align__(16) unsigned ActS[2][16 * 136];  // bf16x2 act, double-buffered
    __shared__ float fuS[304];
    __shared__ float bdS[104], WjS[104];

    int t = threadIdx.x;
    int lane = t & 31, wid = t >> 5;
    int q = lane & 3, r = lane >> 2;
    int c0 = blockIdx.x * 128;
    int b  = b_base + blockIdx.y;

    if (t < 104) {
        bdS[t] = (t < HH) ? bd[t] : 0.f;
        WjS[t] = (t < HH) ? Wj[t] : 0.f;
    }
    for (int i = t; i < DD; i += 256) fuS[i] = g_fu[b * DD + i];

    float acc[13][4];
    #pragma unroll
    for (int nt = 0; nt < 13; nt++)
        #pragma unroll
        for (int k = 0; k < 4; k++) acc[nt][k] = 0.f;

    int cb   = wid * 16;
    int half = t >> 7;             // 0 or 1: which 8 dpairs this thread builds
    int cl   = t & 127;
    int c    = c0 + cl;
    if (c >= CC) c = CC - 1;       // clamp: garbage rows never stored
    const float* cp = g_cand_t + c;

    // rv holds act inputs for the chunk about to be built
    float rv[16];
    #pragma unroll
    for (int i = 0; i < 16; i++) rv[i] = cp[(half * 16 + i) * CC];

    // need fuS before first build
    __syncthreads();
    // build chunk 0 into buf 0
    {
        unsigned* as = &ActS[0][(half * 8) * 136 + cl];
        int dbase = half * 16;
        #pragma unroll
        for (int i = 0; i < 8; i++) {
            float aL = sigt(rv[2 * i]     * fuS[dbase + 2 * i]);
            float aH = sigt(rv[2 * i + 1] * fuS[dbase + 2 * i + 1]);
            as[i * 136] = bf2(aL, aH);
        }
    }
    // load rv for chunk 1
    {
        const float* pn = cp + (32 + half * 16) * CC;
        #pragma unroll
        for (int i = 0; i < 16; i++) rv[i] = pn[i * CC];
    }

    for (int ch = 0; ch < 10; ch++) {
        __syncthreads();                 // buf[ch&1] built by all; buf[(ch+1)&1] free
        // MMA phase on buf[ch&1]
        const unsigned* ab = ActS[ch & 1];
        #pragma unroll
        for (int ks = 0; ks < 2; ks++) {
            int dp = ks * 8 + q;
            unsigned a0 = ab[dp * 136 + cb + r];
            unsigned a1 = ab[dp * 136 + cb + r + 8];
            unsigned a2 = ab[(dp + 4) * 136 + cb + r];
            unsigned a3 = ab[(dp + 4) * 136 + cb + r + 8];
            const uint2* bp = &g_Bfrag[((ch * 2 + ks) * 13) * 32 + lane];
            uint2 bf[13];
            #pragma unroll
            for (int nt = 0; nt < 13; nt++) bf[nt] = bp[nt * 32];
            #pragma unroll
            for (int nt = 0; nt < 13; nt++)
                mma_bf16(acc[nt][0], acc[nt][1], acc[nt][2], acc[nt][3],
                         a0, a1, a2, a3, bf[nt].x, bf[nt].y);
        }
        // build chunk ch+1 into buf[(ch+1)&1]
        if (ch < 9) {
            unsigned* as = &ActS[(ch + 1) & 1][(half * 8) * 136 + cl];
            int dbase = (ch + 1) * 32 + half * 16;
            #pragma unroll
            for (int i = 0; i < 8; i++) {
                int d0 = dbase + 2 * i;
                int d1 = d0 + 1;
                float f0 = fuS[d0 < DD ? d0 : 0];
                float f1 = fuS[d1 < DD ? d1 : 0];
                float aL = sigt(rv[2 * i] * f0);
                float aH = sigt(rv[2 * i + 1] * f1);
                as[i * 136] = bf2(aL, aH);
            }
        }
        // prefetch rv for chunk ch+2 (latency hides under next MMA phase)
        if (ch < 7) {
            const float* pn = cp + ((ch + 2) * 32 + half * 16) * CC;
            #pragma unroll
            for (int i = 0; i < 16; i++) rv[i] = pn[i * CC];
        } else if (ch == 7) {
            int dbn = 288 + half * 16;
            #pragma unroll
            for (int i = 0; i < 16; i++) {
                int d = dbn + i;
                rv[i] = cp[(d < DD ? d : 0) * CC];
            }
        }
    }

    // epilogue
    float pA = 0.f, pB = 0.f;
    #pragma unroll
    for (int nt = 0; nt < 13; nt++) {
        int h0 = nt * 8 + 2 * q;
        float bd0 = bdS[h0], bd1 = bdS[h0 + 1];
        float wj0 = WjS[h0], wj1 = WjS[h0 + 1];
        pA += sigt(acc[nt][0] + bd0) * wj0 + sigt(acc[nt][1] + bd1) * wj1;
        pB += sigt(acc[nt][2] + bd0) * wj0 + sigt(acc[nt][3] + bd1) * wj1;
    }
    pA += __shfl_xor_sync(0xffffffffu, pA, 1);
    pA += __shfl_xor_sync(0xffffffffu, pA, 2);
    pB += __shfl_xor_sync(0xffffffffu, pB, 1);
    pB += __shfl_xor_sync(0xffffffffu, pB, 2);

    if (q == 0) {
        float bjv = bj[0];
        int c1 = c0 + cb + r;
        int c2 = c1 + 8;
        if (c1 < CC) out[b * CC + c1] = pA + bjv;
        if (c2 < CC) out[b * CC + c2] = pB + bjv;
    }
}

// ---------------- 9) finalize: out = 0.5*(y1+y2+y3) + 0.5*ypast ---------------
__global__ void finalize_kernel(const float* __restrict__ ypast,
                                float* __restrict__ out) {
    int idx = blockIdx.x * 256 + threadIdx.x;
    if (idx < BB * CC) {
        int cc = idx % CC;
        out[idx] = 0.5f * (out[idx] + g_y23[cc] + g_y23[CC + cc]) + 0.5f * ypast[idx];
    }
}

// ---------------- launch: b-split pipelined fork-join --------------------------
extern "C" void kernel_launch(void* const* d_in, const int* in_sizes, int n_in,
                              void* d_out, int out_size) {
    const float* utt   = (const float*)d_in[0];
    const float* sys   = (const float*)d_in[1];
    const float* cs    = (const float*)d_in[2];
    const float* cv    = (const float*)d_in[3];
    const float* ypast = (const float*)d_in[4];
    const float* slot  = (const float*)d_in[5];
    const float* val   = (const float*)d_in[6];
    const float* Wc    = (const float*)d_in[7];
    const float* bc    = (const float*)d_in[8];
    const float* w1    = (const float*)d_in[9];
    const float* b1    = (const float*)d_in[10];
    const float* w2    = (const float*)d_in[11];
    const float* b2    = (const float*)d_in[12];
    const float* w3    = (const float*)d_in[13];
    const float* b3    = (const float*)d_in[14];
    const float* Wd    = (const float*)d_in[15];
    const float* bd    = (const float*)d_in[16];
    const float* Wmr   = (const float*)d_in[17];
    const float* bmr   = (const float*)d_in[18];
    const float* Wmc   = (const float*)d_in[19];
    const float* bmc   = (const float*)d_in[20];
    const float* Wj    = (const float*)d_in[21];
    const float* bj    = (const float*)d_in[22];
    float* out = (float*)d_out;

    static cudaStream_t s1 = nullptr, s2 = nullptr, s3 = nullptr;
    static cudaEvent_t eFork, eCand, ePc, eC1, eC2, eY23, eMain;
    if (!s1) {
        // first call is the (uncaptured) correctness run: create infra once
        cudaStreamCreateWithFlags(&s1, cudaStreamNonBlocking);
        cudaStreamCreateWithFlags(&s2, cudaStreamNonBlocking);
        cudaStreamCreateWithFlags(&s3, cudaStreamNonBlocking);
        cudaEventCreateWithFlags(&eFork, cudaEventDisableTiming);
        cudaEventCreateWithFlags(&eCand, cudaEventDisableTiming);
        cudaEventCreateWithFlags(&ePc,   cudaEventDisableTiming);
        cudaEventCreateWithFlags(&eC1,   cudaEventDisableTiming);
        cudaEventCreateWithFlags(&eC2,   cudaEventDisableTiming);
        cudaEventCreateWithFlags(&eY23,  cudaEventDisableTiming);
        cudaEventCreateWithFlags(&eMain, cudaEventDisableTiming);
        cudaFuncSetAttribute(conv_kernel,
                             cudaFuncAttributeMaxDynamicSharedMemorySize, 48 * SX * 4);
    }

    // FORK first (R12-proven): s1/s2/s3 enter the capture graph off stream 0
    cudaEventRecord(eFork, 0);
    cudaStreamWaitEvent(s1, eFork, 0);
    cudaStreamWaitEvent(s2, eFork, 0);
    cudaStreamWaitEvent(s3, eFork, 0);

    // stream 0: conv weights, then conv halves (conv_h1 = 4th call -> ncu slot 3)
    repack_conv_kernel<<<(N_WC + 255) / 256, 256>>>(w1, w2, w3);          // idx 0
    // branch s2: Wd frags + M1 zero, then cand, then pc
    repack_rest_kernel<<<(N_BF + N_M1 + 255) / 256, 256, 0, s2>>>(Wd);    // idx 1
    cand_kernel<<<dim3(63, 3), 256, 0, s2>>>(slot, val, Wc, bc);          // idx 2
    cudaEventRecord(eCand, s2);

    conv_kernel<<<dim3(5, 64), 256, 48 * SX * 4>>>(utt, b1, b2, b3, 0);   // idx 3 (ncu)
    cudaEventRecord(eC1, 0);
    conv_kernel<<<dim3(5, 64), 256, 48 * SX * 4>>>(utt, b1, b2, b3, 64);  // idx 4
    cudaEventRecord(eC2, 0);

    pc_kernel<<<dim3(16, 2), 256, 0, s2>>>(slot, val, cs, cv);            // idx 5
    cudaEventRecord(ePc, s2);

    // side chain on s1: needs full fu (eC2) + Pc & M1-zero (ePc, s2 order)
    cudaStreamWaitEvent(s1, eC2, 0);
    cudaStreamWaitEvent(s1, ePc, 0);
    m1_kernel<<<dim3(3, 75, 4), 128, 0, s1>>>(sys);                       // idx 6
    gemm_rn_kernel<<<dim3(16, 3, 2), 256, 0, s1>>>(slot);                 // idx 7
    y23_kernel<<<dim3(32, 2), 256, 0, s1>>>(Wmr, bmr, Wmc, bmc, Wj, bj);  // idx 8
    cudaEventRecord(eY23, s1);

    // main halves on s3: h1 after conv_h1 + cand/Bfrag; h2 after conv_h2
    cudaStreamWaitEvent(s3, eC1, 0);
    cudaStreamWaitEvent(s3, eCand, 0);
    main_kernel<<<dim3(8, 64), 256, 0, s3>>>(bd, Wj, bj, out, 0);         // idx 9
    cudaStreamWaitEvent(s3, eC2, 0);
    main_kernel<<<dim3(8, 64), 256, 0, s3>>>(bd, Wj, bj, out, 64);        // idx 10
    cudaEventRecord(eMain, s3);

    // JOIN on stream 0: finalize after both mains (eMain) + y23 (eY23)
    cudaStreamWaitEvent(0, eMain, 0);
    cudaStreamWaitEvent(0, eY23, 0);
    finalize_kernel<<<500, 256>>>(ypast, out);                            // idx 11
}